// round 6
// baseline (speedup 1.0000x reference)
#include <cuda_runtime.h>
#include <math.h>

#define TILE   32
#define HALO   34   // TILE + 2
#define CHN    12
#define HIDDEN 128
#define PERC   36
#define OUTC   9    // CHN - GENE_SIZE
#define HW     256
#define PIX    (HW*HW)

// dynamic smem layout (floats)
#define OFF_X    0                         // 12*34*34 = 13872 floats
#define OFF_W1   (OFF_X + CHN*HALO*HALO)   // 128*36 = 4608   (16B aligned)
#define OFF_W2T  (OFF_W1 + HIDDEN*PERC)    // 128*12 = 1536   (16B aligned)
#define OFF_B    (OFF_W2T + HIDDEN*12)     // 128
#define OFF_LIST (OFF_B + HIDDEN)          // 1024 u16 = 512 floats
#define OFF_CNT  (OFF_LIST + 512)          // 1 int
#define SMEM_FLOATS (OFF_CNT + 1)
#define SMEM_BYTES  (SMEM_FLOATS * 4)      // ~83.5 KB

typedef unsigned long long u64;

__device__ __forceinline__ u64 pack2(float lo, float hi) {
    u64 r; asm("mov.b64 %0, {%1, %2};" : "=l"(r) : "f"(lo), "f"(hi)); return r;
}
__device__ __forceinline__ void unpack2(u64 v, float& lo, float& hi) {
    asm("mov.b64 {%0, %1}, %2;" : "=f"(lo), "=f"(hi) : "l"(v));
}
// packed dual FP32 FMA: d = a*b + c elementwise on (lo,hi)
__device__ __forceinline__ u64 ffma2(u64 a, u64 b, u64 c) {
    u64 d; asm("fma.rn.f32x2 %0, %1, %2, %3;" : "=l"(d) : "l"(a), "l"(b), "l"(c)); return d;
}

// perception directly in packed (k,k+1) pair form:
// pp[0..11]  = (x_c, lap_c) pairs   (k = 0..23)
// pp[12..17] = (gn_{2j}, gn_{2j+1}) (k = 24..35)
__device__ __forceinline__ void compute_perc_packed(const float* __restrict__ sx,
                                                    int ty, int tx, u64* pp)
{
    float gn[CHN];
    #pragma unroll
    for (int c = 0; c < CHN; c++) {
        const float* r0 = sx + c * (HALO*HALO) + ty * HALO + tx;
        float n00 = r0[0],        n01 = r0[1],        n02 = r0[2];
        float n10 = r0[HALO],     n11 = r0[HALO+1],   n12 = r0[HALO+2];
        float n20 = r0[2*HALO],   n21 = r0[2*HALO+1], n22 = r0[2*HALO+2];
        float lap = (n00 + n02 + n20 + n22) + 2.0f * (n01 + n10 + n12 + n21) - 12.0f * n11;
        float gxv = (n02 - n00) + 2.0f * (n12 - n10) + (n22 - n20);
        float gyv = (n20 - n00) + 2.0f * (n21 - n01) + (n22 - n02);
        pp[c] = pack2(n11, lap);
        gn[c] = sqrtf(gxv * gxv + gyv * gyv + 1e-8f);
    }
    #pragma unroll
    for (int j = 0; j < 6; j++)
        pp[12 + j] = pack2(gn[2*j], gn[2*j + 1]);
}

__global__ void __launch_bounds__(256)
isoca_fused_kernel(const float* __restrict__ x,
                   const float* __restrict__ rnd,
                   const float* __restrict__ w1w,
                   const float* __restrict__ w1b,
                   const float* __restrict__ w2w,
                   float* __restrict__ out)
{
    extern __shared__ float sm[];
    float* s_x   = sm + OFF_X;
    float* s_w1  = sm + OFF_W1;
    float* s_w2t = sm + OFF_W2T;
    float* s_b   = sm + OFF_B;
    unsigned short* s_list = (unsigned short*)(sm + OFF_LIST);
    int* s_cnt = (int*)(sm + OFF_CNT);

    const int b   = blockIdx.z;
    const int ty0 = blockIdx.y * TILE;
    const int tx0 = blockIdx.x * TILE;
    const int tid = threadIdx.x;

    if (tid == 0) *s_cnt = 0;

    // ---- stage weights ----
    for (int i = tid; i < HIDDEN * PERC; i += 256) s_w1[i] = w1w[i];
    for (int i = tid; i < HIDDEN * 12; i += 256) {
        int h = i / 12, o = i % 12;
        s_w2t[i] = (o < OUTC) ? w2w[o * HIDDEN + h] : 0.0f;
    }
    if (tid < HIDDEN) s_b[tid] = w1b[tid];

    // ---- stage x tile (+1 halo, circular wrap) ----
    const float* xb = x + (size_t)b * CHN * PIX;
    for (int i = tid; i < CHN * HALO * HALO; i += 256) {
        int c  = i / (HALO * HALO);
        int r  = i % (HALO * HALO);
        int yy = r / HALO;
        int xx = r % HALO;
        int gyw = (ty0 + yy - 1) & (HW - 1);
        int gxw = (tx0 + xx - 1) & (HW - 1);
        s_x[c * (HALO*HALO) + yy * HALO + xx] = xb[(size_t)c * PIX + gyw * HW + gxw];
    }
    __syncthreads();

    // =========================== Phase A ===========================
    float* ob = out + (size_t)b * CHN * PIX;

    for (int p = tid; p < TILE * TILE; p += 256) {
        const int ty = p >> 5;
        const int tx = p & 31;
        const int gy = ty0 + ty;
        const int gx = tx0 + tx;
        const size_t pix = (size_t)gy * HW + gx;

        // life gate: 3x3 max-pool of channel 3, NON-circular (-inf edge)
        float mx = -INFINITY;
        #pragma unroll
        for (int dy = -1; dy <= 1; dy++) {
            #pragma unroll
            for (int dx = -1; dx <= 1; dx++) {
                int Y = gy + dy, X = gx + dx;
                if (Y >= 0 && Y < HW && X >= 0 && X < HW)
                    mx = fmaxf(mx, s_x[3*(HALO*HALO) + (ty+1+dy)*HALO + (tx+1+dx)]);
            }
        }
        float life = (mx > 0.1f) ? 1.0f : 0.0f;
        float mask = floorf(rnd[(size_t)b * PIX + pix] + 0.5f);
        bool active = (life * mask) != 0.0f;

        // gene channels always copied
        #pragma unroll
        for (int c = OUTC; c < CHN; c++)
            ob[(size_t)c * PIX + pix] = s_x[c*(HALO*HALO) + (ty+1)*HALO + (tx+1)];

        if (!active) {
            // y * gate == 0 exactly: output = x
            #pragma unroll
            for (int c = 0; c < OUTC; c++)
                ob[(size_t)c * PIX + pix] = s_x[c*(HALO*HALO) + (ty+1)*HALO + (tx+1)];
        } else {
            int idx = atomicAdd(s_cnt, 1);
            s_list[idx] = (unsigned short)p;
        }
    }
    __syncthreads();

    // ===== Phase B: 2 pixels/thread, packed f32x2 MLP, split acc chains =====
    const int n = *s_cnt;

    for (int base = 0; base < n; base += 512) {
        const int i1 = base + tid;
        const int i2 = base + 256 + tid;
        const bool v1 = i1 < n;
        const bool v2 = i2 < n;
        if (!v1) break;

        const int p1 = s_list[i1];
        const int p2 = v2 ? s_list[i2] : 0;
        const int ty1 = p1 >> 5, tx1 = p1 & 31;
        const int ty2 = p2 >> 5, tx2 = p2 & 31;

        u64 p1p[18], p2p[18];
        compute_perc_packed(s_x, ty1, tx1, p1p);
        compute_perc_packed(s_x, ty2, tx2, p2p);  // garbage-safe if !v2 (valid floats, no store)

        // output accumulators: 6 (o,o+1) pairs per pixel (12 padded outs)
        u64 o1p[6], o2p[6];
        #pragma unroll
        for (int i = 0; i < 6; i++) { o1p[i] = 0ull; o2p[i] = 0ull; }

        #pragma unroll 2
        for (int h = 0; h < HIDDEN; h++) {
            const ulonglong2* wr = reinterpret_cast<const ulonglong2*>(s_w1 + h * PERC);
            const float bh = s_b[h];
            // 4 independent chains: (px1,even) (px1,odd) (px2,even) (px2,odd)
            u64 c1a = pack2(bh, 0.0f), c1b = 0ull;
            u64 c2a = c1a,             c2b = 0ull;
            #pragma unroll
            for (int q = 0; q < 9; q++) {
                ulonglong2 w = wr[q];            // LDS.128: two (k,k+1) weight pairs
                c1a = ffma2(w.x, p1p[2*q],   c1a);
                c1b = ffma2(w.y, p1p[2*q+1], c1b);
                c2a = ffma2(w.x, p2p[2*q],   c2a);
                c2b = ffma2(w.y, p2p[2*q+1], c2b);
            }
            float e1, f1, g1, k1, e2, f2, g2, k2;
            unpack2(c1a, e1, f1); unpack2(c1b, g1, k1);
            unpack2(c2a, e2, f2); unpack2(c2b, g2, k2);
            float a1 = (e1 + g1) + (f1 + k1);
            float a2 = (e2 + g2) + (f2 + k2);
            a1 = fmaxf(a1, 0.01f * a1);          // leaky relu (exact)
            a2 = fmaxf(a2, 0.01f * a2);
            u64 a1p = pack2(a1, a1);
            u64 a2p = pack2(a2, a2);

            const ulonglong2* w2r = reinterpret_cast<const ulonglong2*>(s_w2t + h * 12);
            #pragma unroll
            for (int q = 0; q < 3; q++) {
                ulonglong2 w = w2r[q];           // LDS.128: two (o,o+1) pairs
                o1p[2*q]   = ffma2(w.x, a1p, o1p[2*q]);
                o2p[2*q]   = ffma2(w.x, a2p, o2p[2*q]);
                o1p[2*q+1] = ffma2(w.y, a1p, o1p[2*q+1]);
                o2p[2*q+1] = ffma2(w.y, a2p, o2p[2*q+1]);
            }
        }

        // unpack outputs and store
        float o1[12], o2[12];
        #pragma unroll
        for (int q = 0; q < 6; q++) {
            unpack2(o1p[q], o1[2*q], o1[2*q+1]);
            unpack2(o2p[q], o2[2*q], o2[2*q+1]);
        }

        {
            const size_t apix = (size_t)(ty0 + ty1) * HW + (tx0 + tx1);
            #pragma unroll
            for (int c = 0; c < OUTC; c++)
                ob[(size_t)c * PIX + apix] =
                    s_x[c*(HALO*HALO) + (ty1+1)*HALO + (tx1+1)] + o1[c];
        }
        if (v2) {
            const size_t apix = (size_t)(ty0 + ty2) * HW + (tx0 + tx2);
            #pragma unroll
            for (int c = 0; c < OUTC; c++)
                ob[(size_t)c * PIX + apix] =
                    s_x[c*(HALO*HALO) + (ty2+1)*HALO + (tx2+1)] + o2[c];
        }
    }
}

extern "C" void kernel_launch(void* const* d_in, const int* in_sizes, int n_in,
                              void* d_out, int out_size) {
    const float* x   = (const float*)d_in[0];
    const float* rnd = (const float*)d_in[1];
    const float* w1w = (const float*)d_in[2];
    const float* w1b = (const float*)d_in[3];
    const float* w2w = (const float*)d_in[4];
    float* out = (float*)d_out;

    cudaFuncSetAttribute(isoca_fused_kernel,
                         cudaFuncAttributeMaxDynamicSharedMemorySize, SMEM_BYTES);

    dim3 grid(HW / TILE, HW / TILE, 16);   // (8, 8, 16) = 1024 blocks
    isoca_fused_kernel<<<grid, 256, SMEM_BYTES>>>(x, rnd, w1w, w1b, w2w, out);
}

// round 7
// speedup vs baseline: 1.0986x; 1.0986x over previous
#include <cuda_runtime.h>
#include <math.h>

#define TILE   32
#define HALO   34   // TILE + 2
#define CHN    12
#define HIDDEN 128
#define PERC   36
#define PERCP  40   // k padded to 5 mma k-tiles (pad = zeros)
#define OUTC   9
#define HW     256
#define PIX    (HW*HW)

// dynamic smem layout (float units)
#define OFF_X     0                          // 12*34*34 = 13872
#define OFF_W1    (OFF_X + CHN*HALO*HALO)    // 128*40 tf32 bits = 5120
#define OFF_W2T   (OFF_W1 + HIDDEN*PERCP)    // 128*16 tf32 bits = 2048 (o padded to 16, zeros)
#define OFF_B     (OFF_W2T + HIDDEN*16)      // 128 (fp32)
#define OFF_LIST  (OFF_B + HIDDEN)           // 1024 u16 = 512
#define OFF_CNT   (OFF_LIST + 512)           // 4 (padded)
#define OFF_WBUF  (OFF_CNT + 4)              // 8 warps * 16*40 u32 = 5120
#define SMEM_FLOATS (OFF_WBUF + 8*16*40)
#define SMEM_BYTES  (SMEM_FLOATS * 4)        // 107216 B (~104.7 KB)

typedef unsigned int u32;

__device__ __forceinline__ u32 f2tf32(float f) {
    u32 r; asm("cvt.rna.tf32.f32 %0, %1;" : "=r"(r) : "f"(f)); return r;
}

// D(16x8,f32) += A(16x8,tf32,row) * B(8x8,tf32,col); C=D in place
__device__ __forceinline__ void mma_tf32(float& d0, float& d1, float& d2, float& d3,
                                         u32 a0, u32 a1, u32 a2, u32 a3,
                                         u32 b0, u32 b1) {
    asm("mma.sync.aligned.m16n8k8.row.col.f32.tf32.tf32.f32 "
        "{%0,%1,%2,%3}, {%4,%5,%6,%7}, {%8,%9}, {%0,%1,%2,%3};"
        : "+f"(d0), "+f"(d1), "+f"(d2), "+f"(d3)
        : "r"(a0), "r"(a1), "r"(a2), "r"(a3), "r"(b0), "r"(b1));
}

__global__ void __launch_bounds__(256)
isoca_fused_kernel(const float* __restrict__ x,
                   const float* __restrict__ rnd,
                   const float* __restrict__ w1w,
                   const float* __restrict__ w1b,
                   const float* __restrict__ w2w,
                   float* __restrict__ out)
{
    extern __shared__ float sm[];
    float* s_x = sm + OFF_X;
    u32*   s_w1u  = (u32*)(sm + OFF_W1);
    u32*   s_w2u  = (u32*)(sm + OFF_W2T);
    float* s_b    = sm + OFF_B;
    unsigned short* s_list = (unsigned short*)(sm + OFF_LIST);
    int*   s_cnt  = (int*)(sm + OFF_CNT);

    const int b   = blockIdx.z;
    const int ty0 = blockIdx.y * TILE;
    const int tx0 = blockIdx.x * TILE;
    const int tid = threadIdx.x;

    if (tid == 0) *s_cnt = 0;

    // ---- stage weights, pre-converted to tf32 bit patterns ----
    for (int i = tid; i < HIDDEN * PERC; i += 256) {
        int h = i / PERC, k = i % PERC;
        s_w1u[h * PERCP + k] = f2tf32(w1w[i]);
    }
    for (int i = tid; i < HIDDEN * (PERCP - PERC); i += 256) {   // zero k-pad 36..39
        int h = i >> 2, k = PERC + (i & 3);
        s_w1u[h * PERCP + k] = 0u;
    }
    for (int i = tid; i < HIDDEN * 16; i += 256) {               // w2^T [h][o], o padded to 16
        int h = i >> 4, o = i & 15;
        s_w2u[i] = (o < OUTC) ? f2tf32(w2w[o * HIDDEN + h]) : 0u;
    }
    if (tid < HIDDEN) s_b[tid] = w1b[tid];

    // ---- stage x tile (+1 halo, circular wrap) ----
    const float* xb = x + (size_t)b * CHN * PIX;
    for (int i = tid; i < CHN * HALO * HALO; i += 256) {
        int c  = i / (HALO * HALO);
        int r  = i % (HALO * HALO);
        int yy = r / HALO;
        int xx = r % HALO;
        int gyw = (ty0 + yy - 1) & (HW - 1);
        int gxw = (tx0 + xx - 1) & (HW - 1);
        s_x[c * (HALO*HALO) + yy * HALO + xx] = xb[(size_t)c * PIX + gyw * HW + gxw];
    }
    __syncthreads();

    // =========================== Phase A ===========================
    float* ob = out + (size_t)b * CHN * PIX;

    for (int p = tid; p < TILE * TILE; p += 256) {
        const int ty = p >> 5;
        const int tx = p & 31;
        const int gy = ty0 + ty;
        const int gx = tx0 + tx;
        const size_t pix = (size_t)gy * HW + gx;

        // life gate: 3x3 max-pool of channel 3, NON-circular (-inf edge)
        float mx = -INFINITY;
        #pragma unroll
        for (int dy = -1; dy <= 1; dy++) {
            #pragma unroll
            for (int dx = -1; dx <= 1; dx++) {
                int Y = gy + dy, X = gx + dx;
                if (Y >= 0 && Y < HW && X >= 0 && X < HW)
                    mx = fmaxf(mx, s_x[3*(HALO*HALO) + (ty+1+dy)*HALO + (tx+1+dx)]);
            }
        }
        float life = (mx > 0.1f) ? 1.0f : 0.0f;
        float mask = floorf(rnd[(size_t)b * PIX + pix] + 0.5f);
        bool active = (life * mask) != 0.0f;

        // gene channels always copied
        #pragma unroll
        for (int c = OUTC; c < CHN; c++)
            ob[(size_t)c * PIX + pix] = s_x[c*(HALO*HALO) + (ty+1)*HALO + (tx+1)];

        if (!active) {
            #pragma unroll
            for (int c = 0; c < OUTC; c++)
                ob[(size_t)c * PIX + pix] = s_x[c*(HALO*HALO) + (ty+1)*HALO + (tx+1)];
        } else {
            int idx = atomicAdd(s_cnt, 1);
            s_list[idx] = (unsigned short)p;
        }
    }
    __syncthreads();

    // ============ Phase B: tf32 mma over 16-pixel groups per warp ============
    const int n    = *s_cnt;
    const int wid  = tid >> 5;
    const int lane = tid & 31;
    const int g    = lane >> 2;   // 0..7
    const int t    = lane & 3;    // 0..3
    u32* wbuf = (u32*)(sm + OFF_WBUF) + wid * (16 * 40);   // per-warp: perc-buf, then a-buf (aliased)

    const int ngroups = (n + 15) >> 4;
    for (int grp = wid; grp < ngroups; grp += 8) {
        const int base = grp << 4;

        // ---- stage perc[16][40] (tf32 bits): lane = (slot 0..15, half 0..1), 6 channels each ----
        {
            const int slot = lane & 15;
            const int half = lane >> 4;
            int pi = base + slot; if (pi >= n) pi = n - 1;   // clamp (stores skipped later)
            const int pp = s_list[pi];
            const int pty = pp >> 5, ptx = pp & 31;
            #pragma unroll
            for (int j = 0; j < 6; j++) {
                const int c = half * 6 + j;
                const float* r0 = s_x + c * (HALO*HALO) + pty * HALO + ptx;
                float n00 = r0[0],      n01 = r0[1],        n02 = r0[2];
                float n10 = r0[HALO],   n11 = r0[HALO+1],   n12 = r0[HALO+2];
                float n20 = r0[2*HALO], n21 = r0[2*HALO+1], n22 = r0[2*HALO+2];
                float lap = (n00 + n02 + n20 + n22) + 2.0f*(n01 + n10 + n12 + n21) - 12.0f*n11;
                float gxv = (n02 - n00) + 2.0f*(n12 - n10) + (n22 - n20);
                float gyv = (n20 - n00) + 2.0f*(n21 - n01) + (n22 - n02);
                float gn  = sqrtf(gxv*gxv + gyv*gyv + 1e-8f);
                *(uint2*)(wbuf + slot*40 + 2*c) = make_uint2(f2tf32(n11), f2tf32(lap));
                wbuf[slot*40 + 24 + c] = f2tf32(gn);
            }
            *(uint2*)(wbuf + slot*40 + 36 + 2*half) = make_uint2(0u, 0u);   // k-pad
        }
        __syncwarp();

        // ---- A fragments for layer 1 (held for all 128 h) ----
        u32 A[5][4];
        #pragma unroll
        for (int jk = 0; jk < 5; jk++) {
            A[jk][0] = wbuf[ g     *40 + 8*jk + t    ];
            A[jk][1] = wbuf[(g+8)  *40 + 8*jk + t    ];
            A[jk][2] = wbuf[ g     *40 + 8*jk + t + 4];
            A[jk][3] = wbuf[(g+8)  *40 + 8*jk + t + 4];
        }
        __syncwarp();   // perc-buf now free; reuse as a-buf

        float D2[2][4] = {{0,0,0,0},{0,0,0,0}};

        #pragma unroll
        for (int hb = 0; hb < 4; hb++) {       // h-chunk of 32
            // -- layer 1: 4 n-tiles of this chunk --
            #pragma unroll
            for (int jn = 0; jn < 4; jn++) {
                const int h0 = hb*32 + jn*8;
                float2 bb = *(const float2*)(s_b + h0 + 2*t);
                float d0 = bb.x, d1 = bb.y, d2 = bb.x, d3 = bb.y;
                #pragma unroll
                for (int jk = 0; jk < 5; jk++) {
                    u32 b0 = s_w1u[(h0 + g) * PERCP + 8*jk + t    ];
                    u32 b1 = s_w1u[(h0 + g) * PERCP + 8*jk + t + 4];
                    mma_tf32(d0, d1, d2, d3, A[jk][0], A[jk][1], A[jk][2], A[jk][3], b0, b1);
                }
                d0 = fmaxf(d0, 0.01f*d0);  d1 = fmaxf(d1, 0.01f*d1);   // leaky relu
                d2 = fmaxf(d2, 0.01f*d2);  d3 = fmaxf(d3, 0.01f*d3);
                *(uint2*)(wbuf +  g   *40 + jn*8 + 2*t) = make_uint2(f2tf32(d0), f2tf32(d1));
                *(uint2*)(wbuf + (g+8)*40 + jn*8 + 2*t) = make_uint2(f2tf32(d2), f2tf32(d3));
            }
            __syncwarp();
            // -- layer 2: accumulate into D2 --
            #pragma unroll
            for (int jk = 0; jk < 4; jk++) {
                u32 a0 = wbuf[ g   *40 + 8*jk + t    ];
                u32 a1 = wbuf[(g+8)*40 + 8*jk + t    ];
                u32 a2 = wbuf[ g   *40 + 8*jk + t + 4];
                u32 a3 = wbuf[(g+8)*40 + 8*jk + t + 4];
                const int hk = hb*32 + jk*8;
                #pragma unroll
                for (int jo = 0; jo < 2; jo++) {
                    u32 b0 = s_w2u[(hk + t    ) * 16 + jo*8 + g];
                    u32 b1 = s_w2u[(hk + t + 4) * 16 + jo*8 + g];
                    mma_tf32(D2[jo][0], D2[jo][1], D2[jo][2], D2[jo][3],
                             a0, a1, a2, a3, b0, b1);
                }
            }
            __syncwarp();
        }

        // ---- store: px1 = base+g holds (d0,d1); px2 = base+g+8 holds (d2,d3) ----
        const int i1 = base + g;
        const int i2 = base + g + 8;
        if (i1 < n) {
            const int pp = s_list[i1];
            const int pty = pp >> 5, ptx = pp & 31;
            const size_t apix = (size_t)(ty0 + pty) * HW + (tx0 + ptx);
            const int o0 = 2*t;
            ob[(size_t)o0     * PIX + apix] = s_x[o0    *(HALO*HALO) + (pty+1)*HALO + ptx+1] + D2[0][0];
            ob[(size_t)(o0+1) * PIX + apix] = s_x[(o0+1)*(HALO*HALO) + (pty+1)*HALO + ptx+1] + D2[0][1];
            if (t == 0)
                ob[(size_t)8 * PIX + apix] = s_x[8*(HALO*HALO) + (pty+1)*HALO + ptx+1] + D2[1][0];
        }
        if (i2 < n) {
            const int pp = s_list[i2];
            const int pty = pp >> 5, ptx = pp & 31;
            const size_t apix = (size_t)(ty0 + pty) * HW + (tx0 + ptx);
            const int o0 = 2*t;
            ob[(size_t)o0     * PIX + apix] = s_x[o0    *(HALO*HALO) + (pty+1)*HALO + ptx+1] + D2[0][2];
            ob[(size_t)(o0+1) * PIX + apix] = s_x[(o0+1)*(HALO*HALO) + (pty+1)*HALO + ptx+1] + D2[0][3];
            if (t == 0)
                ob[(size_t)8 * PIX + apix] = s_x[8*(HALO*HALO) + (pty+1)*HALO + ptx+1] + D2[1][2];
        }
    }
}

extern "C" void kernel_launch(void* const* d_in, const int* in_sizes, int n_in,
                              void* d_out, int out_size) {
    const float* x   = (const float*)d_in[0];
    const float* rnd = (const float*)d_in[1];
    const float* w1w = (const float*)d_in[2];
    const float* w1b = (const float*)d_in[3];
    const float* w2w = (const float*)d_in[4];
    float* out = (float*)d_out;

    cudaFuncSetAttribute(isoca_fused_kernel,
                         cudaFuncAttributeMaxDynamicSharedMemorySize, SMEM_BYTES);

    dim3 grid(HW / TILE, HW / TILE, 16);   // (8, 8, 16) = 1024 blocks
    isoca_fused_kernel<<<grid, 256, SMEM_BYTES>>>(x, rnd, w1w, w1b, w2w, out);
}

// round 8
// speedup vs baseline: 1.4690x; 1.3372x over previous
#include <cuda_runtime.h>
#include <math.h>

#define TILE   32
#define HALO   34   // TILE + 2
#define CHN    12
#define HIDDEN 128
#define PERC   36
#define OUTC   9
#define HW     256
#define PIX    (HW*HW)

// wbuf: 16 slots, stride 36 u32 (4g mod 32 -> conflict-free A-frag loads)
#define WSTRIDE 36

// dynamic smem layout (float units)
#define OFF_X     0                          // 12*34*34 = 13872
#define OFF_W1F   (OFF_X + CHN*HALO*HALO)    // 16 tiles * 5 k * 32 lanes uint2 = 5120 u32
#define OFF_W2F   (OFF_W1F + 16*5*32*2)      // 4 hb * 4 jk * 2 jo * 32 uint2 = 2048 u32
#define OFF_B     (OFF_W2F + 4*4*2*32*2)     // 128 (fp32)
#define OFF_LIST  (OFF_B + HIDDEN)           // 1024 u16 = 512
#define OFF_CNT   (OFF_LIST + 512)           // 4 (pad, keeps wbuf 8B-aligned)
#define OFF_WBUF  (OFF_CNT + 4)              // 8 warps * 16*36 u32 = 4608
#define SMEM_FLOATS (OFF_WBUF + 8*16*WSTRIDE)
#define SMEM_BYTES  (SMEM_FLOATS * 4)        // ~102.7 KB

typedef unsigned int u32;

__device__ __forceinline__ u32 f2tf32(float f) {
    u32 r; asm("cvt.rna.tf32.f32 %0, %1;" : "=r"(r) : "f"(f)); return r;
}

// D(16x8,f32) += A(16x8,tf32,row) * B(8x8,tf32,col); C=D in place
__device__ __forceinline__ void mma_tf32(float& d0, float& d1, float& d2, float& d3,
                                         u32 a0, u32 a1, u32 a2, u32 a3,
                                         u32 b0, u32 b1) {
    asm("mma.sync.aligned.m16n8k8.row.col.f32.tf32.tf32.f32 "
        "{%0,%1,%2,%3}, {%4,%5,%6,%7}, {%8,%9}, {%0,%1,%2,%3};"
        : "+f"(d0), "+f"(d1), "+f"(d2), "+f"(d3)
        : "r"(a0), "r"(a1), "r"(a2), "r"(a3), "r"(b0), "r"(b1));
}

__global__ void __launch_bounds__(256, 2)
isoca_fused_kernel(const float* __restrict__ x,
                   const float* __restrict__ rnd,
                   const float* __restrict__ w1w,
                   const float* __restrict__ w1b,
                   const float* __restrict__ w2w,
                   float* __restrict__ out)
{
    extern __shared__ float sm[];
    float* s_x   = sm + OFF_X;
    uint2* s_w1f = (uint2*)(sm + OFF_W1F);
    uint2* s_w2f = (uint2*)(sm + OFF_W2F);
    float* s_b   = sm + OFF_B;
    unsigned short* s_list = (unsigned short*)(sm + OFF_LIST);
    int*   s_cnt = (int*)(sm + OFF_CNT);

    const int b    = blockIdx.z;
    const int ty0  = blockIdx.y * TILE;
    const int tx0  = blockIdx.x * TILE;
    const int tid  = threadIdx.x;
    const int wid  = tid >> 5;
    const int lane = tid & 31;
    const int g    = lane >> 2;   // 0..7
    const int t    = lane & 3;    // 0..3

    if (tid == 0) *s_cnt = 0;

    // ---- stage w1 in mma FRAGMENT order: w1frag[tile 0..15][jk 0..4][lane] ----
    // lane (g,t): b0 = w1[h0+g][8jk+t], b1 = w1[h0+g][8jk+t+4]  (k>=36 pads to 0)
    for (int i = tid; i < 16*5*32; i += 256) {
        int l    = i & 31;
        int jk   = (i >> 5) % 5;
        int tile = i / (5*32);
        int lg = l >> 2, lt = l & 3;
        int h  = tile * 8 + lg;
        int k0 = 8*jk + lt;
        int k1 = k0 + 4;
        uint2 v;
        v.x = f2tf32(w1w[h * PERC + k0]);                 // k0 <= 35 always
        v.y = (k1 < PERC) ? f2tf32(w1w[h * PERC + k1]) : 0u;
        s_w1f[i] = v;
    }
    // ---- stage w2 in fragment order: w2frag[hb][jk][jo][lane] ----
    // lane (g,t): b0 = w2[jo*8+g][hk+t], b1 = w2[jo*8+g][hk+t+4]  (o>=9 pads to 0)
    for (int i = tid; i < 4*4*2*32; i += 256) {
        int l  = i & 31;
        int jo = (i >> 5) & 1;
        int jk = (i >> 6) & 3;
        int hb = i >> 8;
        int lg = l >> 2, lt = l & 3;
        int o  = jo * 8 + lg;
        int h0 = hb * 32 + jk * 8;
        uint2 v = make_uint2(0u, 0u);
        if (o < OUTC) {
            v.x = f2tf32(w2w[o * HIDDEN + h0 + lt]);
            v.y = f2tf32(w2w[o * HIDDEN + h0 + lt + 4]);
        }
        s_w2f[i] = v;
    }
    if (tid < HIDDEN) s_b[tid] = w1b[tid];

    // ---- stage x tile (+1 halo, circular wrap) ----
    const float* xb = x + (size_t)b * CHN * PIX;
    for (int i = tid; i < CHN * HALO * HALO; i += 256) {
        int c  = i / (HALO * HALO);
        int r  = i % (HALO * HALO);
        int yy = r / HALO;
        int xx = r % HALO;
        int gyw = (ty0 + yy - 1) & (HW - 1);
        int gxw = (tx0 + xx - 1) & (HW - 1);
        s_x[c * (HALO*HALO) + yy * HALO + xx] = xb[(size_t)c * PIX + gyw * HW + gxw];
    }
    __syncthreads();

    // =========================== Phase A ===========================
    float* ob = out + (size_t)b * CHN * PIX;

    for (int p = tid; p < TILE * TILE; p += 256) {
        const int ty = p >> 5;
        const int tx = p & 31;
        const int gy = ty0 + ty;
        const int gx = tx0 + tx;
        const size_t pix = (size_t)gy * HW + gx;

        // life gate: 3x3 max-pool of channel 3, NON-circular (-inf edge)
        float mx = -INFINITY;
        #pragma unroll
        for (int dy = -1; dy <= 1; dy++) {
            #pragma unroll
            for (int dx = -1; dx <= 1; dx++) {
                int Y = gy + dy, X = gx + dx;
                if (Y >= 0 && Y < HW && X >= 0 && X < HW)
                    mx = fmaxf(mx, s_x[3*(HALO*HALO) + (ty+1+dy)*HALO + (tx+1+dx)]);
            }
        }
        float life = (mx > 0.1f) ? 1.0f : 0.0f;
        float mask = floorf(rnd[(size_t)b * PIX + pix] + 0.5f);
        bool active = (life * mask) != 0.0f;

        #pragma unroll
        for (int c = OUTC; c < CHN; c++)
            ob[(size_t)c * PIX + pix] = s_x[c*(HALO*HALO) + (ty+1)*HALO + (tx+1)];

        if (!active) {
            #pragma unroll
            for (int c = 0; c < OUTC; c++)
                ob[(size_t)c * PIX + pix] = s_x[c*(HALO*HALO) + (ty+1)*HALO + (tx+1)];
        } else {
            int idx = atomicAdd(s_cnt, 1);
            s_list[idx] = (unsigned short)p;
        }
    }
    __syncthreads();

    // ============ Phase B: tf32 mma over 16-pixel groups per warp ============
    const int n = *s_cnt;
    u32* wbuf = (u32*)(sm + OFF_WBUF) + wid * (16 * WSTRIDE);

    // hoist layer-2 B fragments into registers (reused across all groups)
    uint2 W2[4][4][2];
    #pragma unroll
    for (int hb = 0; hb < 4; hb++)
        #pragma unroll
        for (int jk = 0; jk < 4; jk++)
            #pragma unroll
            for (int jo = 0; jo < 2; jo++)
                W2[hb][jk][jo] = s_w2f[(((hb*4 + jk)*2) + jo)*32 + lane];

    const int ngroups = (n + 15) >> 4;
    for (int grp = wid; grp < ngroups; grp += 8) {
        const int base = grp << 4;

        // ---- stage perc[16][36] tf32: lane = (slot 0..15, half 0..1), 6 chans each ----
        {
            const int slot = lane & 15;
            const int half = lane >> 4;
            int pi = base + slot; if (pi >= n) pi = n - 1;   // clamp (stores guarded later)
            const int pp = s_list[pi];
            const int pty = pp >> 5, ptx = pp & 31;
            #pragma unroll
            for (int j = 0; j < 6; j++) {
                const int c = half * 6 + j;
                const float* r0 = s_x + c * (HALO*HALO) + pty * HALO + ptx;
                float n00 = r0[0],      n01 = r0[1],        n02 = r0[2];
                float n10 = r0[HALO],   n11 = r0[HALO+1],   n12 = r0[HALO+2];
                float n20 = r0[2*HALO], n21 = r0[2*HALO+1], n22 = r0[2*HALO+2];
                float lap = (n00 + n02 + n20 + n22) + 2.0f*(n01 + n10 + n12 + n21) - 12.0f*n11;
                float gxv = (n02 - n00) + 2.0f*(n12 - n10) + (n22 - n20);
                float gyv = (n20 - n00) + 2.0f*(n21 - n01) + (n22 - n02);
                float gn  = sqrtf(gxv*gxv + gyv*gyv + 1e-8f);
                *(uint2*)(wbuf + slot*WSTRIDE + 2*c) = make_uint2(f2tf32(n11), f2tf32(lap));
                wbuf[slot*WSTRIDE + 24 + c] = f2tf32(gn);
            }
        }
        __syncwarp();

        // ---- A fragments for layer 1 (k-pad tile jk=4 upper half forced to 0) ----
        u32 A[5][4];
        #pragma unroll
        for (int jk = 0; jk < 5; jk++) {
            A[jk][0] = wbuf[ g    *WSTRIDE + 8*jk + t    ];
            A[jk][1] = wbuf[(g+8) *WSTRIDE + 8*jk + t    ];
            A[jk][2] = (jk < 4) ? wbuf[ g    *WSTRIDE + 8*jk + t + 4] : 0u;
            A[jk][3] = (jk < 4) ? wbuf[(g+8) *WSTRIDE + 8*jk + t + 4] : 0u;
        }
        __syncwarp();   // perc-buf now free; reuse as activation buffer

        float D2[2][4] = {{0,0,0,0},{0,0,0,0}};

        #pragma unroll
        for (int hb = 0; hb < 4; hb++) {       // h-chunk of 32
            // -- layer 1: 4 n-tiles --
            #pragma unroll
            for (int jn = 0; jn < 4; jn++) {
                const int tile = hb*4 + jn;    // h0 = tile*8
                float2 bb = *(const float2*)(s_b + tile*8 + 2*t);
                float d0 = bb.x, d1 = bb.y, d2 = bb.x, d3 = bb.y;
                const uint2* w1p = s_w1f + tile*5*32 + lane;
                #pragma unroll
                for (int jk = 0; jk < 5; jk++) {
                    uint2 w = w1p[jk*32];     // one LDS.64, conflict-free
                    mma_tf32(d0, d1, d2, d3, A[jk][0], A[jk][1], A[jk][2], A[jk][3], w.x, w.y);
                }
                d0 = fmaxf(d0, 0.01f*d0);  d1 = fmaxf(d1, 0.01f*d1);   // leaky relu
                d2 = fmaxf(d2, 0.01f*d2);  d3 = fmaxf(d3, 0.01f*d3);
                *(uint2*)(wbuf +  g   *WSTRIDE + jn*8 + 2*t) = make_uint2(f2tf32(d0), f2tf32(d1));
                *(uint2*)(wbuf + (g+8)*WSTRIDE + jn*8 + 2*t) = make_uint2(f2tf32(d2), f2tf32(d3));
            }
            __syncwarp();
            // -- layer 2: accumulate into D2 (B fragments in registers) --
            #pragma unroll
            for (int jk = 0; jk < 4; jk++) {
                u32 a0 = wbuf[ g   *WSTRIDE + 8*jk + t    ];
                u32 a1 = wbuf[(g+8)*WSTRIDE + 8*jk + t    ];
                u32 a2 = wbuf[ g   *WSTRIDE + 8*jk + t + 4];
                u32 a3 = wbuf[(g+8)*WSTRIDE + 8*jk + t + 4];
                #pragma unroll
                for (int jo = 0; jo < 2; jo++) {
                    uint2 w = W2[hb][jk][jo];
                    mma_tf32(D2[jo][0], D2[jo][1], D2[jo][2], D2[jo][3],
                             a0, a1, a2, a3, w.x, w.y);
                }
            }
            __syncwarp();
        }

        // ---- store: px1 = base+g holds (d0,d1); px2 = base+g+8 holds (d2,d3) ----
        const int i1 = base + g;
        const int i2 = base + g + 8;
        if (i1 < n) {
            const int pp = s_list[i1];
            const int pty = pp >> 5, ptx = pp & 31;
            const size_t apix = (size_t)(ty0 + pty) * HW + (tx0 + ptx);
            const int o0 = 2*t;
            ob[(size_t)o0     * PIX + apix] = s_x[o0    *(HALO*HALO) + (pty+1)*HALO + ptx+1] + D2[0][0];
            ob[(size_t)(o0+1) * PIX + apix] = s_x[(o0+1)*(HALO*HALO) + (pty+1)*HALO + ptx+1] + D2[0][1];
            if (t == 0)
                ob[(size_t)8 * PIX + apix] = s_x[8*(HALO*HALO) + (pty+1)*HALO + ptx+1] + D2[1][0];
        }
        if (i2 < n) {
            const int pp = s_list[i2];
            const int pty = pp >> 5, ptx = pp & 31;
            const size_t apix = (size_t)(ty0 + pty) * HW + (tx0 + ptx);
            const int o0 = 2*t;
            ob[(size_t)o0     * PIX + apix] = s_x[o0    *(HALO*HALO) + (pty+1)*HALO + ptx+1] + D2[0][2];
            ob[(size_t)(o0+1) * PIX + apix] = s_x[(o0+1)*(HALO*HALO) + (pty+1)*HALO + ptx+1] + D2[0][3];
            if (t == 0)
                ob[(size_t)8 * PIX + apix] = s_x[8*(HALO*HALO) + (pty+1)*HALO + ptx+1] + D2[1][2];
        }
    }
}

extern "C" void kernel_launch(void* const* d_in, const int* in_sizes, int n_in,
                              void* d_out, int out_size) {
    const float* x   = (const float*)d_in[0];
    const float* rnd = (const float*)d_in[1];
    const float* w1w = (const float*)d_in[2];
    const float* w1b = (const float*)d_in[3];
    const float* w2w = (const float*)d_in[4];
    float* out = (float*)d_out;

    cudaFuncSetAttribute(isoca_fused_kernel,
                         cudaFuncAttributeMaxDynamicSharedMemorySize, SMEM_BYTES);

    dim3 grid(HW / TILE, HW / TILE, 16);   // (8, 8, 16) = 1024 blocks
    isoca_fused_kernel<<<grid, 256, SMEM_BYTES>>>(x, rnd, w1w, w1b, w2w, out);
}

// round 9
// speedup vs baseline: 1.6077x; 1.0944x over previous
#include <cuda_runtime.h>
#include <math.h>

#define TILE   32
#define HALO   34   // TILE + 2
#define CHN    12
#define HIDDEN 128
#define PERC   36
#define OUTC   9
#define HW     256
#define PIX    (HW*HW)

// wbuf: 16 slots, stride 36 u32 (4g+t mod 32 distinct -> conflict-free A-frag loads)
#define WSTRIDE 36

// dynamic smem layout (float units)
#define OFF_X     0                          // 12*34*34 = 13872
#define OFF_W1F   (OFF_X + CHN*HALO*HALO)    // 16 tiles * 5 k * 32 lanes uint2 = 5120 u32
#define OFF_W2F   (OFF_W1F + 16*5*32*2)      // 4 hb * 4 jk * 2 jo * 32 uint2 = 2048 u32
#define OFF_B     (OFF_W2F + 4*4*2*32*2)     // 128 (fp32)
#define OFF_LIST  (OFF_B + HIDDEN)           // 1024 u16 = 512
#define OFF_CNT   (OFF_LIST + 512)           // 4 (pad, keeps wbuf 8B-aligned)
#define OFF_WBUF  (OFF_CNT + 4)              // 8 warps * 16*36 u32 = 4608
#define SMEM_FLOATS (OFF_WBUF + 8*16*WSTRIDE)
#define SMEM_BYTES  (SMEM_FLOATS * 4)        // ~102.7 KB

typedef unsigned int u32;

__device__ __forceinline__ u32 f2tf32(float f) {
    u32 r; asm("cvt.rna.tf32.f32 %0, %1;" : "=r"(r) : "f"(f)); return r;
}

// D(16x8,f32) += A(16x8,tf32,row) * B(8x8,tf32,col); C=D in place
__device__ __forceinline__ void mma_tf32(float& d0, float& d1, float& d2, float& d3,
                                         u32 a0, u32 a1, u32 a2, u32 a3,
                                         u32 b0, u32 b1) {
    asm("mma.sync.aligned.m16n8k8.row.col.f32.tf32.tf32.f32 "
        "{%0,%1,%2,%3}, {%4,%5,%6,%7}, {%8,%9}, {%0,%1,%2,%3};"
        : "+f"(d0), "+f"(d1), "+f"(d2), "+f"(d3)
        : "r"(a0), "r"(a1), "r"(a2), "r"(a3), "r"(b0), "r"(b1));
}

// stage perc for 16 pixel slots into wbuf (tf32 bits), lane = (slot 0..15, half 0..1)
__device__ __forceinline__ void stage_perc(u32* wbuf, const float* s_x,
                                           const unsigned short* s_list,
                                           int base, int n, int lane)
{
    const int slot = lane & 15;
    const int half = lane >> 4;
    int pi = base + slot; if (pi >= n) pi = n - 1;   // clamp (stores guarded later)
    const int pp = s_list[pi];
    const int pty = pp >> 5, ptx = pp & 31;
    #pragma unroll
    for (int j = 0; j < 6; j++) {
        const int c = half * 6 + j;
        const float* r0 = s_x + c * (HALO*HALO) + pty * HALO + ptx;
        float n00 = r0[0],      n01 = r0[1],        n02 = r0[2];
        float n10 = r0[HALO],   n11 = r0[HALO+1],   n12 = r0[HALO+2];
        float n20 = r0[2*HALO], n21 = r0[2*HALO+1], n22 = r0[2*HALO+2];
        float lap = (n00 + n02 + n20 + n22) + 2.0f*(n01 + n10 + n12 + n21) - 12.0f*n11;
        float gxv = (n02 - n00) + 2.0f*(n12 - n10) + (n22 - n20);
        float gyv = (n20 - n00) + 2.0f*(n21 - n01) + (n22 - n02);
        float gn  = sqrtf(gxv*gxv + gyv*gyv + 1e-8f);
        *(uint2*)(wbuf + slot*WSTRIDE + 2*c) = make_uint2(f2tf32(n11), f2tf32(lap));
        wbuf[slot*WSTRIDE + 24 + c] = f2tf32(gn);
    }
}

__device__ __forceinline__ void load_A(const u32* wbuf, int g, int t, u32 A[5][4]) {
    #pragma unroll
    for (int jk = 0; jk < 5; jk++) {
        A[jk][0] = wbuf[ g    *WSTRIDE + 8*jk + t    ];
        A[jk][1] = wbuf[(g+8) *WSTRIDE + 8*jk + t    ];
        A[jk][2] = (jk < 4) ? wbuf[ g    *WSTRIDE + 8*jk + t + 4] : 0u;
        A[jk][3] = (jk < 4) ? wbuf[(g+8) *WSTRIDE + 8*jk + t + 4] : 0u;
    }
}

// leaky-relu + tf32-cvt + shuffle D(m16n8) fragment into A(m16k8) fragment, in registers
__device__ __forceinline__ void d_to_a(float d0, float d1, float d2, float d3,
                                       int lane, int t,
                                       u32& a0, u32& a1, u32& a2, u32& a3)
{
    d0 = fmaxf(d0, 0.01f*d0);  d1 = fmaxf(d1, 0.01f*d1);
    d2 = fmaxf(d2, 0.01f*d2);  d3 = fmaxf(d3, 0.01f*d3);
    u32 u0 = f2tf32(d0), u1 = f2tf32(d1), u2 = f2tf32(d2), u3 = f2tf32(d3);
    const int src0 = (lane & ~3) | (t >> 1);   // quad-local lane holding col t
    const int src1 = src0 + 2;                 // holding col t+4
    u32 e00 = __shfl_sync(0xffffffffu, u0, src0);
    u32 e01 = __shfl_sync(0xffffffffu, u1, src0);
    u32 e10 = __shfl_sync(0xffffffffu, u2, src0);
    u32 e11 = __shfl_sync(0xffffffffu, u3, src0);
    u32 f00 = __shfl_sync(0xffffffffu, u0, src1);
    u32 f01 = __shfl_sync(0xffffffffu, u1, src1);
    u32 f10 = __shfl_sync(0xffffffffu, u2, src1);
    u32 f11 = __shfl_sync(0xffffffffu, u3, src1);
    const bool odd = (t & 1);
    a0 = odd ? e01 : e00;   // (row g,   col t)
    a1 = odd ? e11 : e10;   // (row g+8, col t)
    a2 = odd ? f01 : f00;   // (row g,   col t+4)
    a3 = odd ? f11 : f10;   // (row g+8, col t+4)
}

__global__ void __launch_bounds__(256, 2)
isoca_fused_kernel(const float* __restrict__ x,
                   const float* __restrict__ rnd,
                   const float* __restrict__ w1w,
                   const float* __restrict__ w1b,
                   const float* __restrict__ w2w,
                   float* __restrict__ out)
{
    extern __shared__ float sm[];
    float* s_x   = sm + OFF_X;
    uint2* s_w1f = (uint2*)(sm + OFF_W1F);
    uint2* s_w2f = (uint2*)(sm + OFF_W2F);
    float* s_b   = sm + OFF_B;
    unsigned short* s_list = (unsigned short*)(sm + OFF_LIST);
    int*   s_cnt = (int*)(sm + OFF_CNT);

    const int b    = blockIdx.z;
    const int ty0  = blockIdx.y * TILE;
    const int tx0  = blockIdx.x * TILE;
    const int tid  = threadIdx.x;
    const int wid  = tid >> 5;
    const int lane = tid & 31;
    const int g    = lane >> 2;   // 0..7
    const int t    = lane & 3;    // 0..3

    if (tid == 0) *s_cnt = 0;

    // ---- stage w1 in mma FRAGMENT order: w1frag[tile 0..15][jk 0..4][lane] ----
    for (int i = tid; i < 16*5*32; i += 256) {
        int l    = i & 31;
        int jk   = (i >> 5) % 5;
        int tile = i / (5*32);
        int lg = l >> 2, lt = l & 3;
        int h  = tile * 8 + lg;
        int k0 = 8*jk + lt;
        int k1 = k0 + 4;
        uint2 v;
        v.x = f2tf32(w1w[h * PERC + k0]);
        v.y = (k1 < PERC) ? f2tf32(w1w[h * PERC + k1]) : 0u;
        s_w1f[i] = v;
    }
    // ---- stage w2 in fragment order: w2frag[hb][jk][jo][lane] ----
    for (int i = tid; i < 4*4*2*32; i += 256) {
        int l  = i & 31;
        int jo = (i >> 5) & 1;
        int jk = (i >> 6) & 3;
        int hb = i >> 8;
        int lg = l >> 2, lt = l & 3;
        int o  = jo * 8 + lg;
        int h0 = hb * 32 + jk * 8;
        uint2 v = make_uint2(0u, 0u);
        if (o < OUTC) {
            v.x = f2tf32(w2w[o * HIDDEN + h0 + lt]);
            v.y = f2tf32(w2w[o * HIDDEN + h0 + lt + 4]);
        }
        s_w2f[i] = v;
    }
    if (tid < HIDDEN) s_b[tid] = w1b[tid];

    // ---- stage x tile (+1 halo, circular wrap) ----
    const float* xb = x + (size_t)b * CHN * PIX;
    for (int i = tid; i < CHN * HALO * HALO; i += 256) {
        int c  = i / (HALO * HALO);
        int r  = i % (HALO * HALO);
        int yy = r / HALO;
        int xx = r % HALO;
        int gyw = (ty0 + yy - 1) & (HW - 1);
        int gxw = (tx0 + xx - 1) & (HW - 1);
        s_x[c * (HALO*HALO) + yy * HALO + xx] = xb[(size_t)c * PIX + gyw * HW + gxw];
    }
    __syncthreads();

    // =========================== Phase A ===========================
    float* ob = out + (size_t)b * CHN * PIX;

    for (int p = tid; p < TILE * TILE; p += 256) {
        const int ty = p >> 5;
        const int tx = p & 31;
        const int gy = ty0 + ty;
        const int gx = tx0 + tx;
        const size_t pix = (size_t)gy * HW + gx;

        float mx = -INFINITY;
        #pragma unroll
        for (int dy = -1; dy <= 1; dy++) {
            #pragma unroll
            for (int dx = -1; dx <= 1; dx++) {
                int Y = gy + dy, X = gx + dx;
                if (Y >= 0 && Y < HW && X >= 0 && X < HW)
                    mx = fmaxf(mx, s_x[3*(HALO*HALO) + (ty+1+dy)*HALO + (tx+1+dx)]);
            }
        }
        float life = (mx > 0.1f) ? 1.0f : 0.0f;
        float mask = floorf(rnd[(size_t)b * PIX + pix] + 0.5f);
        bool active = (life * mask) != 0.0f;

        #pragma unroll
        for (int c = OUTC; c < CHN; c++)
            ob[(size_t)c * PIX + pix] = s_x[c*(HALO*HALO) + (ty+1)*HALO + (tx+1)];

        if (!active) {
            #pragma unroll
            for (int c = 0; c < OUTC; c++)
                ob[(size_t)c * PIX + pix] = s_x[c*(HALO*HALO) + (ty+1)*HALO + (tx+1)];
        } else {
            int idx = atomicAdd(s_cnt, 1);
            s_list[idx] = (unsigned short)p;
        }
    }
    __syncthreads();

    // ====== Phase B: 32 pixels (2 mma groups) per warp iteration, tf32 mma ======
    const int n = *s_cnt;
    u32* wbuf = (u32*)(sm + OFF_WBUF) + wid * (16 * WSTRIDE);

    const int ngroups = (n + 15) >> 4;
    const int npairs  = (ngroups + 1) >> 1;
    for (int pr = wid; pr < npairs; pr += 8) {
        const int base0 = pr << 5;
        const int base1 = base0 + 16;

        // ---- stage + load A fragments for both groups ----
        stage_perc(wbuf, s_x, s_list, base0, n, lane);
        __syncwarp();
        u32 A0[5][4]; load_A(wbuf, g, t, A0);
        __syncwarp();
        stage_perc(wbuf, s_x, s_list, base1, n, lane);   // clamped if base1 >= n
        __syncwarp();
        u32 A1[5][4]; load_A(wbuf, g, t, A1);

        float D2a[2][4] = {{0,0,0,0},{0,0,0,0}};
        float D2b[2][4] = {{0,0,0,0},{0,0,0,0}};

        #pragma unroll
        for (int hb = 0; hb < 4; hb++) {
            #pragma unroll
            for (int jn = 0; jn < 4; jn++) {
                const int tile = hb*4 + jn;    // layer-1 n-tile, h0 = tile*8
                float2 bb = *(const float2*)(s_b + tile*8 + 2*t);
                float d0a = bb.x, d1a = bb.y, d2a = bb.x, d3a = bb.y;
                float d0b = bb.x, d1b = bb.y, d2b = bb.x, d3b = bb.y;
                const uint2* w1p = s_w1f + tile*5*32 + lane;
                #pragma unroll
                for (int jk = 0; jk < 5; jk++) {
                    uint2 w = w1p[jk*32];      // one LDS.64, shared by both groups
                    mma_tf32(d0a, d1a, d2a, d3a, A0[jk][0], A0[jk][1], A0[jk][2], A0[jk][3], w.x, w.y);
                    mma_tf32(d0b, d1b, d2b, d3b, A1[jk][0], A1[jk][1], A1[jk][2], A1[jk][3], w.x, w.y);
                }
                // leaky + cvt + in-register D->A transpose (no smem, no syncwarp)
                u32 a0a, a1a, a2a, a3a, a0b, a1b, a2b, a3b;
                d_to_a(d0a, d1a, d2a, d3a, lane, t, a0a, a1a, a2a, a3a);
                d_to_a(d0b, d1b, d2b, d3b, lane, t, a0b, a1b, a2b, a3b);
                // layer 2, k-tile = jn within chunk hb
                #pragma unroll
                for (int jo = 0; jo < 2; jo++) {
                    uint2 w = s_w2f[((tile)*2 + jo)*32 + lane];   // shared by both groups
                    mma_tf32(D2a[jo][0], D2a[jo][1], D2a[jo][2], D2a[jo][3],
                             a0a, a1a, a2a, a3a, w.x, w.y);
                    mma_tf32(D2b[jo][0], D2b[jo][1], D2b[jo][2], D2b[jo][3],
                             a0b, a1b, a2b, a3b, w.x, w.y);
                }
            }
        }

        // ---- stores: group0 pixels base0+g / base0+g+8; group1 likewise ----
        #pragma unroll
        for (int grp2 = 0; grp2 < 2; grp2++) {
            const int  gb = grp2 ? base1 : base0;
            float (*D2)[4] = grp2 ? D2b : D2a;
            const int i1 = gb + g;
            const int i2 = gb + g + 8;
            if (i1 < n) {
                const int pp = s_list[i1];
                const int pty = pp >> 5, ptx = pp & 31;
                const size_t apix = (size_t)(ty0 + pty) * HW + (tx0 + ptx);
                const int o0 = 2*t;
                ob[(size_t)o0     * PIX + apix] = s_x[o0    *(HALO*HALO) + (pty+1)*HALO + ptx+1] + D2[0][0];
                ob[(size_t)(o0+1) * PIX + apix] = s_x[(o0+1)*(HALO*HALO) + (pty+1)*HALO + ptx+1] + D2[0][1];
                if (t == 0)
                    ob[(size_t)8 * PIX + apix] = s_x[8*(HALO*HALO) + (pty+1)*HALO + ptx+1] + D2[1][0];
            }
            if (i2 < n) {
                const int pp = s_list[i2];
                const int pty = pp >> 5, ptx = pp & 31;
                const size_t apix = (size_t)(ty0 + pty) * HW + (tx0 + ptx);
                const int o0 = 2*t;
                ob[(size_t)o0     * PIX + apix] = s_x[o0    *(HALO*HALO) + (pty+1)*HALO + ptx+1] + D2[0][2];
                ob[(size_t)(o0+1) * PIX + apix] = s_x[(o0+1)*(HALO*HALO) + (pty+1)*HALO + ptx+1] + D2[0][3];
                if (t == 0)
                    ob[(size_t)8 * PIX + apix] = s_x[8*(HALO*HALO) + (pty+1)*HALO + ptx+1] + D2[1][2];
            }
        }
    }
}

extern "C" void kernel_launch(void* const* d_in, const int* in_sizes, int n_in,
                              void* d_out, int out_size) {
    const float* x   = (const float*)d_in[0];
    const float* rnd = (const float*)d_in[1];
    const float* w1w = (const float*)d_in[2];
    const float* w1b = (const float*)d_in[3];
    const float* w2w = (const float*)d_in[4];
    float* out = (float*)d_out;

    cudaFuncSetAttribute(isoca_fused_kernel,
                         cudaFuncAttributeMaxDynamicSharedMemorySize, SMEM_BYTES);

    dim3 grid(HW / TILE, HW / TILE, 16);   // (8, 8, 16) = 1024 blocks
    isoca_fused_kernel<<<grid, 256, SMEM_BYTES>>>(x, rnd, w1w, w1b, w2w, out);
}

// round 10
// speedup vs baseline: 1.7633x; 1.0968x over previous
#include <cuda_runtime.h>
#include <math.h>

#define TILE   32
#define HALO   34   // TILE + 2
#define CHN    12
#define HIDDEN 128
#define PERC   36
#define OUTC   9
#define HW     256
#define PIX    (HW*HW)

// wbuf: 16 slots, stride 36 u32 (4g+t mod 32 distinct -> conflict-free A-frag loads)
#define WSTRIDE 36

// dynamic smem layout (float units)
#define OFF_X     0                          // 12*34*34 = 13872
#define OFF_W1F   (OFF_X + CHN*HALO*HALO)    // 16 tiles * 5 k * 32 lanes uint2 = 5120 u32
#define OFF_W2F   (OFF_W1F + 16*5*32*2)      // 16 tiles * 2 jo * 32 lanes uint2 = 2048 u32
#define OFF_B     (OFF_W2F + 16*2*32*2)      // 128 (fp32)
#define OFF_LIST  (OFF_B + HIDDEN)           // 1024 u16 = 512
#define OFF_CNT   (OFF_LIST + 512)           // 4 (pad, keeps wbuf 8B-aligned)
#define OFF_WBUF  (OFF_CNT + 4)              // 8 warps * 16*36 u32 = 4608
#define SMEM_FLOATS (OFF_WBUF + 8*16*WSTRIDE)
#define SMEM_BYTES  (SMEM_FLOATS * 4)        // ~102.7 KB

typedef unsigned int u32;

__device__ __forceinline__ u32 f2tf32(float f) {
    u32 r; asm("cvt.rna.tf32.f32 %0, %1;" : "=r"(r) : "f"(f)); return r;
}

// D(16x8,f32) += A(16x8,tf32,row) * B(8x8,tf32,col); C=D in place
__device__ __forceinline__ void mma_tf32(float& d0, float& d1, float& d2, float& d3,
                                         u32 a0, u32 a1, u32 a2, u32 a3,
                                         u32 b0, u32 b1) {
    asm("mma.sync.aligned.m16n8k8.row.col.f32.tf32.tf32.f32 "
        "{%0,%1,%2,%3}, {%4,%5,%6,%7}, {%8,%9}, {%0,%1,%2,%3};"
        : "+f"(d0), "+f"(d1), "+f"(d2), "+f"(d3)
        : "r"(a0), "r"(a1), "r"(a2), "r"(a3), "r"(b0), "r"(b1));
}

// stage perc for 16 pixel slots into wbuf (tf32 bits), lane = (slot 0..15, half 0..1)
__device__ __forceinline__ void stage_perc(u32* wbuf, const float* s_x,
                                           const unsigned short* s_list,
                                           int base, int n, int lane)
{
    const int slot = lane & 15;
    const int half = lane >> 4;
    int pi = base + slot; if (pi >= n) pi = n - 1;   // clamp (stores guarded later)
    const int pp = s_list[pi];
    const int pty = pp >> 5, ptx = pp & 31;
    #pragma unroll
    for (int j = 0; j < 6; j++) {
        const int c = half * 6 + j;
        const float* r0 = s_x + c * (HALO*HALO) + pty * HALO + ptx;
        float n00 = r0[0],      n01 = r0[1],        n02 = r0[2];
        float n10 = r0[HALO],   n11 = r0[HALO+1],   n12 = r0[HALO+2];
        float n20 = r0[2*HALO], n21 = r0[2*HALO+1], n22 = r0[2*HALO+2];
        float lap = (n00 + n02 + n20 + n22) + 2.0f*(n01 + n10 + n12 + n21) - 12.0f*n11;
        float gxv = (n02 - n00) + 2.0f*(n12 - n10) + (n22 - n20);
        float gyv = (n20 - n00) + 2.0f*(n21 - n01) + (n22 - n02);
        float gn  = sqrtf(gxv*gxv + gyv*gyv + 1e-8f);
        *(uint2*)(wbuf + slot*WSTRIDE + 2*c) = make_uint2(f2tf32(n11), f2tf32(lap));
        wbuf[slot*WSTRIDE + 24 + c] = f2tf32(gn);
    }
}

__device__ __forceinline__ void load_A(const u32* wbuf, int g, int t, u32 A[5][4]) {
    #pragma unroll
    for (int jk = 0; jk < 5; jk++) {
        A[jk][0] = wbuf[ g    *WSTRIDE + 8*jk + t    ];
        A[jk][1] = wbuf[(g+8) *WSTRIDE + 8*jk + t    ];
        A[jk][2] = (jk < 4) ? wbuf[ g    *WSTRIDE + 8*jk + t + 4] : 0u;
        A[jk][3] = (jk < 4) ? wbuf[(g+8) *WSTRIDE + 8*jk + t + 4] : 0u;
    }
}

__global__ void __launch_bounds__(256, 2)
isoca_fused_kernel(const float* __restrict__ x,
                   const float* __restrict__ rnd,
                   const float* __restrict__ w1w,
                   const float* __restrict__ w1b,
                   const float* __restrict__ w2w,
                   float* __restrict__ out)
{
    extern __shared__ float sm[];
    float* s_x   = sm + OFF_X;
    uint2* s_w1f = (uint2*)(sm + OFF_W1F);
    uint2* s_w2f = (uint2*)(sm + OFF_W2F);
    float* s_b   = sm + OFF_B;
    unsigned short* s_list = (unsigned short*)(sm + OFF_LIST);
    int*   s_cnt = (int*)(sm + OFF_CNT);

    const int b    = blockIdx.z;
    const int ty0  = blockIdx.y * TILE;
    const int tx0  = blockIdx.x * TILE;
    const int tid  = threadIdx.x;
    const int wid  = tid >> 5;
    const int lane = tid & 31;
    const int g    = lane >> 2;   // 0..7
    const int t    = lane & 3;    // 0..3

    if (tid == 0) *s_cnt = 0;

    // ---- stage w1 in mma FRAGMENT order: w1frag[tile 0..15][jk 0..4][lane] ----
    for (int i = tid; i < 16*5*32; i += 256) {
        int l    = i & 31;
        int jk   = (i >> 5) % 5;
        int tile = i / (5*32);
        int lg = l >> 2, lt = l & 3;
        int h  = tile * 8 + lg;
        int k0 = 8*jk + lt;
        int k1 = k0 + 4;
        uint2 v;
        v.x = f2tf32(w1w[h * PERC + k0]);
        v.y = (k1 < PERC) ? f2tf32(w1w[h * PERC + k1]) : 0u;
        s_w1f[i] = v;
    }
    // ---- stage w2 in PERMUTED fragment order: w2frag[tile][jo][lane] ----
    // k-slot permutation: slot lt -> h0+2*lt, slot lt+4 -> h0+2*lt+1, so layer-1 D
    // registers (cols 2t,2t+1) are directly a valid layer-2 A fragment.
    for (int i = tid; i < 16*2*32; i += 256) {
        int l    = i & 31;
        int jo   = (i >> 5) & 1;
        int tile = i >> 6;
        int lg = l >> 2, lt = l & 3;
        int o  = jo * 8 + lg;
        int h0 = tile * 8;
        uint2 v = make_uint2(0u, 0u);
        if (o < OUTC) {
            v.x = f2tf32(w2w[o * HIDDEN + h0 + 2*lt    ]);   // k-slot lt
            v.y = f2tf32(w2w[o * HIDDEN + h0 + 2*lt + 1]);   // k-slot lt+4
        }
        s_w2f[i] = v;
    }
    if (tid < HIDDEN) s_b[tid] = w1b[tid];

    // ---- stage x tile (+1 halo, circular wrap) ----
    const float* xb = x + (size_t)b * CHN * PIX;
    for (int i = tid; i < CHN * HALO * HALO; i += 256) {
        int c  = i / (HALO * HALO);
        int r  = i % (HALO * HALO);
        int yy = r / HALO;
        int xx = r % HALO;
        int gyw = (ty0 + yy - 1) & (HW - 1);
        int gxw = (tx0 + xx - 1) & (HW - 1);
        s_x[c * (HALO*HALO) + yy * HALO + xx] = xb[(size_t)c * PIX + gyw * HW + gxw];
    }
    __syncthreads();

    // =========================== Phase A ===========================
    float* ob = out + (size_t)b * CHN * PIX;

    for (int p = tid; p < TILE * TILE; p += 256) {
        const int ty = p >> 5;
        const int tx = p & 31;
        const int gy = ty0 + ty;
        const int gx = tx0 + tx;
        const size_t pix = (size_t)gy * HW + gx;

        float mx = -INFINITY;
        #pragma unroll
        for (int dy = -1; dy <= 1; dy++) {
            #pragma unroll
            for (int dx = -1; dx <= 1; dx++) {
                int Y = gy + dy, X = gx + dx;
                if (Y >= 0 && Y < HW && X >= 0 && X < HW)
                    mx = fmaxf(mx, s_x[3*(HALO*HALO) + (ty+1+dy)*HALO + (tx+1+dx)]);
            }
        }
        float life = (mx > 0.1f) ? 1.0f : 0.0f;
        float mask = floorf(rnd[(size_t)b * PIX + pix] + 0.5f);
        bool active = (life * mask) != 0.0f;

        #pragma unroll
        for (int c = OUTC; c < CHN; c++)
            ob[(size_t)c * PIX + pix] = s_x[c*(HALO*HALO) + (ty+1)*HALO + (tx+1)];

        if (!active) {
            #pragma unroll
            for (int c = 0; c < OUTC; c++)
                ob[(size_t)c * PIX + pix] = s_x[c*(HALO*HALO) + (ty+1)*HALO + (tx+1)];
        } else {
            int idx = atomicAdd(s_cnt, 1);
            s_list[idx] = (unsigned short)p;
        }
    }
    __syncthreads();

    // ====== Phase B: 32 pixels (2 mma groups) per warp iteration, tf32 mma ======
    const int n = *s_cnt;
    u32* wbuf = (u32*)(sm + OFF_WBUF) + wid * (16 * WSTRIDE);

    const int ngroups = (n + 15) >> 4;
    const int npairs  = (ngroups + 1) >> 1;
    for (int pr = wid; pr < npairs; pr += 8) {
        const int base0 = pr << 5;
        const int base1 = base0 + 16;

        // ---- stage + load A fragments for both groups ----
        stage_perc(wbuf, s_x, s_list, base0, n, lane);
        __syncwarp();
        u32 A0[5][4]; load_A(wbuf, g, t, A0);
        __syncwarp();
        stage_perc(wbuf, s_x, s_list, base1, n, lane);   // clamped if base1 >= n
        __syncwarp();
        u32 A1[5][4]; load_A(wbuf, g, t, A1);

        float D2a[2][4] = {{0,0,0,0},{0,0,0,0}};
        float D2b[2][4] = {{0,0,0,0},{0,0,0,0}};

        #pragma unroll
        for (int tile = 0; tile < 16; tile++) {     // layer-1 n-tile, h0 = tile*8
            float2 bb = *(const float2*)(s_b + tile*8 + 2*t);
            float d0a = bb.x, d1a = bb.y, d2a = bb.x, d3a = bb.y;
            float d0b = bb.x, d1b = bb.y, d2b = bb.x, d3b = bb.y;
            const uint2* w1p = s_w1f + tile*5*32 + lane;
            #pragma unroll
            for (int jk = 0; jk < 5; jk++) {
                uint2 w = w1p[jk*32];      // one LDS.64, shared by both groups
                mma_tf32(d0a, d1a, d2a, d3a, A0[jk][0], A0[jk][1], A0[jk][2], A0[jk][3], w.x, w.y);
                mma_tf32(d0b, d1b, d2b, d3b, A1[jk][0], A1[jk][1], A1[jk][2], A1[jk][3], w.x, w.y);
            }
            // leaky + cvt: D fragment IS the layer-2 A fragment (k-perm baked into w2f)
            u32 a0a = f2tf32(fmaxf(d0a, 0.01f*d0a));
            u32 a2a = f2tf32(fmaxf(d1a, 0.01f*d1a));
            u32 a1a = f2tf32(fmaxf(d2a, 0.01f*d2a));
            u32 a3a = f2tf32(fmaxf(d3a, 0.01f*d3a));
            u32 a0b = f2tf32(fmaxf(d0b, 0.01f*d0b));
            u32 a2b = f2tf32(fmaxf(d1b, 0.01f*d1b));
            u32 a1b = f2tf32(fmaxf(d2b, 0.01f*d2b));
            u32 a3b = f2tf32(fmaxf(d3b, 0.01f*d3b));
            const uint2* w2p = s_w2f + tile*2*32 + lane;
            #pragma unroll
            for (int jo = 0; jo < 2; jo++) {
                uint2 w = w2p[jo*32];      // one LDS.64, shared by both groups
                mma_tf32(D2a[jo][0], D2a[jo][1], D2a[jo][2], D2a[jo][3],
                         a0a, a1a, a2a, a3a, w.x, w.y);
                mma_tf32(D2b[jo][0], D2b[jo][1], D2b[jo][2], D2b[jo][3],
                         a0b, a1b, a2b, a3b, w.x, w.y);
            }
        }

        // ---- stores: group0 pixels base0+g / base0+g+8; group1 likewise ----
        #pragma unroll
        for (int grp2 = 0; grp2 < 2; grp2++) {
            const int  gb = grp2 ? base1 : base0;
            float (*D2)[4] = grp2 ? D2b : D2a;
            const int i1 = gb + g;
            const int i2 = gb + g + 8;
            if (i1 < n) {
                const int pp = s_list[i1];
                const int pty = pp >> 5, ptx = pp & 31;
                const size_t apix = (size_t)(ty0 + pty) * HW + (tx0 + ptx);
                const int o0 = 2*t;
                ob[(size_t)o0     * PIX + apix] = s_x[o0    *(HALO*HALO) + (pty+1)*HALO + ptx+1] + D2[0][0];
                ob[(size_t)(o0+1) * PIX + apix] = s_x[(o0+1)*(HALO*HALO) + (pty+1)*HALO + ptx+1] + D2[0][1];
                if (t == 0)
                    ob[(size_t)8 * PIX + apix] = s_x[8*(HALO*HALO) + (pty+1)*HALO + ptx+1] + D2[1][0];
            }
            if (i2 < n) {
                const int pp = s_list[i2];
                const int pty = pp >> 5, ptx = pp & 31;
                const size_t apix = (size_t)(ty0 + pty) * HW + (tx0 + ptx);
                const int o0 = 2*t;
                ob[(size_t)o0     * PIX + apix] = s_x[o0    *(HALO*HALO) + (pty+1)*HALO + ptx+1] + D2[0][2];
                ob[(size_t)(o0+1) * PIX + apix] = s_x[(o0+1)*(HALO*HALO) + (pty+1)*HALO + ptx+1] + D2[0][3];
                if (t == 0)
                    ob[(size_t)8 * PIX + apix] = s_x[8*(HALO*HALO) + (pty+1)*HALO + ptx+1] + D2[1][2];
            }
        }
    }
}

extern "C" void kernel_launch(void* const* d_in, const int* in_sizes, int n_in,
                              void* d_out, int out_size) {
    const float* x   = (const float*)d_in[0];
    const float* rnd = (const float*)d_in[1];
    const float* w1w = (const float*)d_in[2];
    const float* w1b = (const float*)d_in[3];
    const float* w2w = (const float*)d_in[4];
    float* out = (float*)d_out;

    cudaFuncSetAttribute(isoca_fused_kernel,
                         cudaFuncAttributeMaxDynamicSharedMemorySize, SMEM_BYTES);

    dim3 grid(HW / TILE, HW / TILE, 16);   // (8, 8, 16) = 1024 blocks
    isoca_fused_kernel<<<grid, 256, SMEM_BYTES>>>(x, rnd, w1w, w1b, w2w, out);
}